// round 10
// baseline (speedup 1.0000x reference)
#include <cuda_runtime.h>
#include <cuda_fp16.h>
#include <math.h>

#define BATCH 32768
#define FEAT  40
#define DCOLS 496
#define NT    1000

__device__ float g_la[NT], g_l1ma[NT], g_lca[NT], g_l1mca[NT];
__device__ float g_cs_part[8][DCOLS];
__device__ float g_colsum[DCOLS];
__device__ float g_row_loss[BATCH];
__device__ __align__(16) unsigned short g_Whalf[DCOLS * DCOLS];   // fp16 copy of W

__constant__ float c_lognc[5] = {0.69314718055994531f, 1.38629436111989062f,
                                 2.07944154167983593f, 2.77258872223978124f,
                                 3.46573590279972655f};
__constant__ int c_off[5] = {0, 2, 6, 14, 30};

#define CLOG (-69.07755278982137f)   // log(1e-30)

// fast logaddexp (rel err ~1e-7, budget is 1e-3)
__device__ __forceinline__ float flae(float a, float b) {
    float mx = fmaxf(a, b);
    return mx + __logf(1.0f + __expf(-fabsf(a - b)));
}

__device__ __forceinline__ float wred(float v) {
    #pragma unroll
    for (int o = 16; o; o >>= 1) v += __shfl_down_sync(0xffffffffu, v, o);
    return v;
}

// ---------------------------------------------------------------------------
// Fused: W -> fp16 conversion + partial column sums (single pass over W).
// ---------------------------------------------------------------------------
__global__ void wcs_kernel(const float* __restrict__ W) {
    int j  = blockIdx.x * 128 + threadIdx.x;
    int r0 = blockIdx.y * 62;
    if (j < DCOLS) {
        float s0 = 0.f, s1 = 0.f;
        #pragma unroll
        for (int d = 0; d < 62; d += 2) {
            float w0 = W[(size_t)(r0 + d) * DCOLS + j];
            float w1 = W[(size_t)(r0 + d + 1) * DCOLS + j];
            s0 += w0; s1 += w1;
            g_Whalf[(size_t)(r0 + d)     * DCOLS + j] = __half_as_ushort(__float2half_rn(w0));
            g_Whalf[(size_t)(r0 + d + 1) * DCOLS + j] = __half_as_ushort(__float2half_rn(w1));
        }
        g_cs_part[blockIdx.y][j] = s0 + s1;
    }
}

// ---------------------------------------------------------------------------
// Fused: diffusion schedule (block 0) + colsum combine (blocks 1-4).
// Runs after wcs_kernel, so cs_part is complete.
// ---------------------------------------------------------------------------
__global__ void sched_comb_kernel() {
    if (blockIdx.x == 0) {
        __shared__ float s[1024];
        int t = threadIdx.x;
        float la = 0.0f;
        if (t < NT) {
            float beta = (t == NT - 1) ? 0.02f : (1e-4f + (float)t * ((0.02f - 1e-4f) / 999.0f));
            la = log1pf(-beta);
            g_la[t]   = la;
            g_l1ma[t] = logf(beta);
        }
        s[t] = la;
        __syncthreads();
        for (int off = 1; off < 1024; off <<= 1) {
            float v = (t >= off) ? s[t - off] : 0.0f;
            __syncthreads();
            s[t] += v;
            __syncthreads();
        }
        if (t < NT) {
            float lc = s[t];
            g_lca[t]   = lc;
            g_l1mca[t] = logf(-expm1f(lc));
        }
    } else {
        int j = (blockIdx.x - 1) * 128 + threadIdx.x;
        if (threadIdx.x < 128 && j < DCOLS) {
            float s = 0.f;
            #pragma unroll
            for (int i = 0; i < 8; i++) s += g_cs_part[i][j];
            g_colsum[j] = s;
        }
    }
}

// ---------------------------------------------------------------------------
// Main: one block per batch row, 128 threads.
// Phases 1/3/4: thread t (t<124) owns columns 4t..4t+3.
// Gather phase: thread t (t<62) owns columns 8t..8t+7 (LDG.128 fp16).
// ---------------------------------------------------------------------------
__global__ void __launch_bounds__(128, 16) ddpm_kernel(
    const int*   __restrict__ x0,
    const int*   __restrict__ tsteps,
    const float* __restrict__ uni,
    const float* __restrict__ bias,
    const float* __restrict__ temb)
{
    const int b   = blockIdx.x;
    const int tid = threadIdx.x;

    __shared__ __align__(16) float sm[DCOLS];
    __shared__ int    s_col0[FEAT];
    __shared__ int    s_wbyte[FEAT];
    __shared__ float2 s_lp[FEAT];      // {lpo, lp0} q_prior logits
    __shared__ float4 s_fc[FEAT];      // {lse_pred, e0, B, unused} for dense accum
    __shared__ float  s_red[3][4];

    const int   t    = tsteps[b];
    const int   tm1  = (t > 0) ? t - 1 : 0;
    const float lca1 = g_lca[tm1], l1mca1 = g_l1mca[tm1];
    const float Aev  = (t == 0) ? 1.0f : __expf(lca1);     // uniform per block

    // scanner-thread persistent state
    int c0 = 0, w = 0;

    // -------- setup: per-feature q_prior logits + x0 column --------
    if (tid < FEAT) {
        const float lca = g_lca[t], l1mca = g_l1mca[t];
        int f = tid, g = f / 5, k = f - 5 * g;
        int start = g * 62 + c_off[k];
        float lognc = c_lognc[k];
        c0 = start + x0[b * FEAT + f];
        s_col0[f] = c0;
        s_lp[f] = make_float2(flae(CLOG + lca, l1mca - lognc),   // elsewhere
                              flae(lca,        l1mca - lognc));  // at x0 col
    }

    const int  j0  = tid * 4;
    const bool act = (j0 < DCOLS);

    // packed feature ids for this thread's 4 columns
    unsigned int fpack = 0;
    if (act) {
        #pragma unroll
        for (int q = 0; q < 4; q++) {
            int j = j0 + q;
            int g = j / 62, o = j - 62 * g;
            int k = (o < 2) ? 0 : (o < 6) ? 1 : (o < 14) ? 2 : (o < 30) ? 3 : 4;
            fpack |= (unsigned int)(5 * g + k) << (8 * q);
        }
    }
    __syncthreads();

    // -------- phase 1: z = gumbel + q_prior logits --------
    if (act) {
        float4 u4 = *reinterpret_cast<const float4*>(uni + (size_t)b * DCOLS + j0);
        const float* up = reinterpret_cast<const float*>(&u4);
        float4 z; float* zp = reinterpret_cast<float*>(&z);
        #pragma unroll
        for (int q = 0; q < 4; q++) {
            int j = j0 + q;
            int f = (fpack >> (8 * q)) & 0xff;
            float gum = -__logf(-__logf(up[q] + 1e-30f) + 1e-30f);
            float2 lp = s_lp[f];
            zp[q] = gum + ((j == s_col0[f]) ? lp.y : lp.x);
        }
        *reinterpret_cast<float4*>(sm + j0) = z;
    }
    __syncthreads();

    // per-segment argmax (first-max tie break; segment starts even -> float2)
    if (tid < FEAT) {
        int f = tid, g = f / 5, k = f - 5 * g;
        int start = g * 62 + c_off[k], n2 = (2 << k) >> 1;
        const float2* p2 = reinterpret_cast<const float2*>(sm + start);
        float best = -3.4e38f; int bi = 0;
        for (int i = 0; i < n2; i++) {
            float2 v = p2[i];
            if (v.x > best) { best = v.x; bi = 2 * i; }
            if (v.y > best) { best = v.y; bi = 2 * i + 1; }
        }
        w = start + bi;
        s_wbyte[f] = w * (DCOLS * 2);          // byte offset into fp16 W row
    }
    __syncthreads();

    // -------- phase 2: gather-sum of 40 fp16 W rows (62 thr x 8 cols) ------
    if (tid < 62) {
        const char* Wb = (const char*)g_Whalf + (size_t)tid * 16;
        __half2 a0 = __floats2half2_rn(0.f, 0.f), a1 = a0, a2 = a0, a3 = a0;
        #pragma unroll 8
        for (int f = 0; f < FEAT; f++) {
            uint4 v = *reinterpret_cast<const uint4*>(Wb + s_wbyte[f]);
            a0 = __hadd2(a0, *reinterpret_cast<__half2*>(&v.x));
            a1 = __hadd2(a1, *reinterpret_cast<__half2*>(&v.y));
            a2 = __hadd2(a2, *reinterpret_cast<__half2*>(&v.z));
            a3 = __hadd2(a3, *reinterpret_cast<__half2*>(&v.w));
        }
        float2 s01 = __half22float2(a0), s23 = __half22float2(a1);
        float2 s45 = __half22float2(a2), s67 = __half22float2(a3);
        int jj = tid * 8;
        float4 cs0 = *reinterpret_cast<const float4*>(g_colsum + jj);
        float4 cs1 = *reinterpret_cast<const float4*>(g_colsum + jj + 4);
        float4 bb0 = *reinterpret_cast<const float4*>(bias + jj);
        float4 bb1 = *reinterpret_cast<const float4*>(bias + jj + 4);
        const float* tb = temb + (size_t)t * DCOLS + jj;
        float4 te0 = *reinterpret_cast<const float4*>(tb);
        float4 te1 = *reinterpret_cast<const float4*>(tb + 4);
        float4 p0, p1;
        p0.x = CLOG * (cs0.x - s01.x) + bb0.x + te0.x;
        p0.y = CLOG * (cs0.y - s01.y) + bb0.y + te0.y;
        p0.z = CLOG * (cs0.z - s23.x) + bb0.z + te0.z;
        p0.w = CLOG * (cs0.w - s23.y) + bb0.w + te0.w;
        p1.x = CLOG * (cs1.x - s45.x) + bb1.x + te1.x;
        p1.y = CLOG * (cs1.y - s45.y) + bb1.y + te1.y;
        p1.z = CLOG * (cs1.z - s67.x) + bb1.z + te1.z;
        p1.w = CLOG * (cs1.w - s67.y) + bb1.w + te1.w;
        *reinterpret_cast<float4*>(sm + jj)     = p0;
        *reinterpret_cast<float4*>(sm + jj + 4) = p1;
    }
    __syncthreads();

    // -------- scanner: lse(pred), true posterior, closed-form lse2, corrections --
    float kl = 0.f, dec = 0.f, pr = 0.f;
    if (tid < FEAT) {
        int f = tid, g = f / 5, k = f - 5 * g;
        int start = g * 62 + c_off[k], wdt = 2 << k, n2 = wdt >> 1;
        float lognc = c_lognc[k];

        const float2* p2 = reinterpret_cast<const float2*>(sm + start);
        float m = -3.4e38f;
        for (int i = 0; i < n2; i++) {
            float2 v = p2[i];
            m = fmaxf(m, fmaxf(v.x, v.y));
        }
        float s = 0.f;
        for (int i = 0; i < n2; i++) {
            float2 v = p2[i];
            s += __expf(v.x - m) + __expf(v.y - m);
        }
        float lse = m + __logf(s);

        // per-feature q_one_timestep values (only scanner needs them)
        const float la = g_la[t], l1ma = g_l1ma[t];
        float q1w = flae(la,        l1ma - lognc);
        float q1o = flae(CLOG + la, l1ma - lognc);

        // true posterior closed form
        float ev0 = (t == 0) ? 0.f  : flae(lca1,        l1mca1 - lognc);
        float evo = (t == 0) ? CLOG : flae(CLOG + lca1, l1mca1 - lognc);
        float un_oo = evo + q1o;
        float e0, e1, e2, klc, sum_p;
        if (c0 == w) {
            float un_b = ev0 + q1w;
            float mm = fmaxf(un_b, un_oo);
            float ss = __expf(un_b - mm) + (float)(wdt - 1) * __expf(un_oo - mm);
            float l2 = mm + __logf(ss);
            float lt1 = un_b - l2, lt0 = un_oo - l2;
            e0 = __expf(lt0); e1 = __expf(lt1); e2 = e1;
            klc = e1 * lt1 + (float)(wdt - 1) * e0 * lt0;
            sum_p = e1 + (float)(wdt - 1) * e0;
        } else {
            float un_c0 = ev0 + q1o;
            float un_w  = evo + q1w;
            float mm = fmaxf(fmaxf(un_c0, un_w), un_oo);
            float ss = __expf(un_c0 - mm) + __expf(un_w - mm) + (float)(wdt - 2) * __expf(un_oo - mm);
            float l2 = mm + __logf(ss);
            float lt0 = un_oo - l2, lt1 = un_c0 - l2, lt2 = un_w - l2;
            e0 = __expf(lt0); e1 = __expf(lt1); e2 = __expf(lt2);
            klc = e1 * lt1 + e2 * lt2 + (float)(wdt - 2) * e0 * lt0;
            sum_p = e1 + e2 + (float)(wdt - 2) * e0;
        }

        // est-posterior pieces at c0 and w + closed-form lse2
        float Bev = (t == 0) ? 0.f : __expf(l1mca1 - lognc);
        float pc0 = sm[c0], pw = sm[w];
        float smw  = __expf(pw  - lse);
        float smc0 = __expf(pc0 - lse);
        float ev_c0 = (t == 0) ? (pc0 - lse) : __logf(fmaf(smc0, Aev, Bev));
        float ev_w  = (t == 0) ? (pw  - lse) : __logf(fmaf(smw,  Aev, Bev));
        float qwE = __expf(q1w), qoE = __expf(q1o);
        float Z = Aev * fmaf(qwE - qoE, smw, qoE) + Bev * (qwE + (float)(wdt - 1) * qoE);
        float lse2 = __logf(Z);

        // scanner-side KL correction and decoder NLL
        float corr;
        float q1c0;
        if (c0 == w) {
            corr = klc + (lse2 - q1o) * sum_p - (e1 - e0) * ev_c0 - (q1w - q1o) * e1;
            q1c0 = q1w;
        } else {
            corr = klc + (lse2 - q1o) * sum_p - (e1 - e0) * ev_c0 - (e2 - e0) * ev_w
                 - (q1w - q1o) * e2;
            q1c0 = q1o;
        }
        kl  = corr;
        dec = lse2 - ev_c0 - q1c0;

        s_fc[f] = make_float4(lse, e0, Bev, 0.f);
    }
    if (tid < 5) {                              // kl_prior: 5 distinct values x 8 groups
        float lognc = c_lognc[tid];
        float wdt = (float)(2 << tid);
        float lcaT = g_lca[NT - 1], l1mcaT = g_l1mca[NT - 1];
        float lq0 = flae(lcaT,        l1mcaT - lognc);
        float lqo = flae(CLOG + lcaT, l1mcaT - lognc);
        pr = 8.0f * (__expf(lq0) * (lq0 + lognc) + (wdt - 1.0f) * __expf(lqo) * (lqo + lognc));
    }
    __syncthreads();

    // -------- dense accumulation: kl -= e0 * ev_j over all columns --------
    if (act) {
        float4 pv = *reinterpret_cast<const float4*>(sm + j0);
        const float* pp = reinterpret_cast<const float*>(&pv);
        #pragma unroll
        for (int q = 0; q < 4; q++) {
            int f = (fpack >> (8 * q)) & 0xff;
            float4 fc = s_fc[f];
            float lh = pp[q] - fc.x;
            float ev = (t == 0) ? lh : __logf(fmaf(__expf(lh), Aev, fc.z));
            kl -= fc.y * ev;
        }
    }

    float rk = wred(kl), rd = wred(dec), rp = wred(pr);
    int wid = tid >> 5, lane = tid & 31;
    if (lane == 0) { s_red[0][wid] = rk; s_red[1][wid] = rd; s_red[2][wid] = rp; }
    __syncthreads();
    if (tid == 0) {
        float K  = s_red[0][0] + s_red[0][1] + s_red[0][2] + s_red[0][3];
        float Dn = s_red[1][0] + s_red[1][1] + s_red[1][2] + s_red[1][3];
        float P  = s_red[2][0] + s_red[2][1] + s_red[2][2] + s_red[2][3];
        float diff = (t == 0) ? Dn : K;
        g_row_loss[b] = diff * 1000.0f + P;
    }
}

__global__ void reduce_kernel(float* __restrict__ out) {
    __shared__ double sd[32];
    int tid = threadIdx.x;
    double s = 0.0;
    const float4* rl = reinterpret_cast<const float4*>(g_row_loss);
    for (int i = tid; i < BATCH / 4; i += 1024) {
        float4 v = rl[i];
        s += (double)v.x + (double)v.y + (double)v.z + (double)v.w;
    }
    #pragma unroll
    for (int o = 16; o; o >>= 1) s += __shfl_down_sync(0xffffffffu, s, o);
    if ((tid & 31) == 0) sd[tid >> 5] = s;
    __syncthreads();
    if (tid < 32) {
        double v = sd[tid];
        #pragma unroll
        for (int o = 16; o; o >>= 1) v += __shfl_down_sync(0xffffffffu, v, o);
        if (tid == 0) out[0] = (float)(v / (double)BATCH);
    }
}

extern "C" void kernel_launch(void* const* d_in, const int* in_sizes, int n_in,
                              void* d_out, int out_size)
{
    const int*   x0 = nullptr;  const int*   ts = nullptr;
    const float* un = nullptr;  const float* W  = nullptr;
    const float* bi = nullptr;  const float* te = nullptr;
    for (int i = 0; i < n_in; i++) {
        switch (in_sizes[i]) {
            case BATCH * FEAT:   x0 = (const int*)d_in[i];   break;
            case BATCH:          ts = (const int*)d_in[i];   break;
            case BATCH * DCOLS:  un = (const float*)d_in[i]; break;
            case DCOLS * DCOLS:  W  = (const float*)d_in[i]; break;
            case DCOLS:          bi = (const float*)d_in[i]; break;
            case NT * DCOLS:     te = (const float*)d_in[i]; break;
            default: break;
        }
    }
    float* out = (float*)d_out;

    dim3 gcs(4, 8);
    wcs_kernel<<<gcs, 128>>>(W);          // fp16 W + partial colsums
    sched_comb_kernel<<<5, 1024>>>();     // schedule + colsum combine
    ddpm_kernel<<<BATCH, 128>>>(x0, ts, un, bi, te);
    reduce_kernel<<<1, 1024>>>(out);
}

// round 12
// speedup vs baseline: 1.4144x; 1.4144x over previous
#include <cuda_runtime.h>
#include <cuda_fp16.h>
#include <math.h>

#define BATCH 32768
#define FEAT  40
#define DCOLS 496
#define NT    1000

__device__ float g_la[NT], g_l1ma[NT], g_lca[NT], g_l1mca[NT];
__device__ float g_cs_part[8][DCOLS];
__device__ float g_colsum[DCOLS];
__device__ float g_row_loss[BATCH];
__device__ double g_part[64];
__device__ __align__(16) unsigned short g_Whalf[DCOLS * DCOLS];   // fp16 copy of W

__constant__ float c_lognc[5] = {0.69314718055994531f, 1.38629436111989062f,
                                 2.07944154167983593f, 2.77258872223978124f,
                                 3.46573590279972655f};
__constant__ int c_off[5] = {0, 2, 6, 14, 30};

#define CLOG (-69.07755278982137f)   // log(1e-30)

// fast logaddexp (rel err ~1e-7, budget is 1e-3)
__device__ __forceinline__ float flae(float a, float b) {
    float mx = fmaxf(a, b);
    return mx + __logf(1.0f + __expf(-fabsf(a - b)));
}

__device__ __forceinline__ float wred(float v) {
    #pragma unroll
    for (int o = 16; o; o >>= 1) v += __shfl_down_sync(0xffffffffu, v, o);
    return v;
}

// ---------------------------------------------------------------------------
// Fused: W -> fp16 conversion + partial column sums (single pass over W).
// ---------------------------------------------------------------------------
__global__ void wcs_kernel(const float* __restrict__ W) {
    int j  = blockIdx.x * 128 + threadIdx.x;
    int r0 = blockIdx.y * 62;
    if (j < DCOLS) {
        float s0 = 0.f, s1 = 0.f;
        #pragma unroll
        for (int d = 0; d < 62; d += 2) {
            float w0 = W[(size_t)(r0 + d) * DCOLS + j];
            float w1 = W[(size_t)(r0 + d + 1) * DCOLS + j];
            s0 += w0; s1 += w1;
            g_Whalf[(size_t)(r0 + d)     * DCOLS + j] = __half_as_ushort(__float2half_rn(w0));
            g_Whalf[(size_t)(r0 + d + 1) * DCOLS + j] = __half_as_ushort(__float2half_rn(w1));
        }
        g_cs_part[blockIdx.y][j] = s0 + s1;
    }
}

// ---------------------------------------------------------------------------
// Fused: diffusion schedule (block 0) + colsum combine (blocks 1-4).
// ---------------------------------------------------------------------------
__global__ void sched_comb_kernel() {
    if (blockIdx.x == 0) {
        __shared__ float s[1024];
        int t = threadIdx.x;
        float la = 0.0f;
        if (t < NT) {
            float beta = (t == NT - 1) ? 0.02f : (1e-4f + (float)t * ((0.02f - 1e-4f) / 999.0f));
            la = log1pf(-beta);
            g_la[t]   = la;
            g_l1ma[t] = logf(beta);
        }
        s[t] = la;
        __syncthreads();
        for (int off = 1; off < 1024; off <<= 1) {
            float v = (t >= off) ? s[t - off] : 0.0f;
            __syncthreads();
            s[t] += v;
            __syncthreads();
        }
        if (t < NT) {
            float lc = s[t];
            g_lca[t]   = lc;
            g_l1mca[t] = logf(-expm1f(lc));
        }
    } else {
        int j = (blockIdx.x - 1) * 128 + threadIdx.x;
        if (threadIdx.x < 128 && j < DCOLS) {
            float s = 0.f;
            #pragma unroll
            for (int i = 0; i < 8; i++) s += g_cs_part[i][j];
            g_colsum[j] = s;
        }
    }
}

// ---------------------------------------------------------------------------
// Main: one block per batch row, 128 threads; thread t owns columns 4t..4t+3.
// (Gather spread over 124 threads — 4 warps — for latency hiding.)
// ---------------------------------------------------------------------------
__global__ void __launch_bounds__(128, 16) ddpm_kernel(
    const int*   __restrict__ x0,
    const int*   __restrict__ tsteps,
    const float* __restrict__ uni,
    const float* __restrict__ bias,
    const float* __restrict__ temb)
{
    const int b   = blockIdx.x;
    const int tid = threadIdx.x;

    __shared__ __align__(16) float sm[DCOLS];
    __shared__ int    s_col0[FEAT];
    __shared__ int    s_wbyte[FEAT];
    __shared__ float2 s_lp[FEAT];      // {lpo, lp0} q_prior logits
    __shared__ float4 s_fc[FEAT];      // {lse_pred, e0, B, unused} for dense accum
    __shared__ float  s_red[3][4];

    const int   t    = tsteps[b];
    const int   tm1  = (t > 0) ? t - 1 : 0;
    const float lca1 = g_lca[tm1], l1mca1 = g_l1mca[tm1];
    const float Aev  = (t == 0) ? 1.0f : __expf(lca1);     // uniform per block

    // scanner-thread persistent state
    int c0 = 0, w = 0;

    // -------- setup: per-feature q_prior logits + x0 column --------
    if (tid < FEAT) {
        const float lca = g_lca[t], l1mca = g_l1mca[t];
        int f = tid, g = f / 5, k = f - 5 * g;
        int start = g * 62 + c_off[k];
        float lognc = c_lognc[k];
        c0 = start + x0[b * FEAT + f];
        s_col0[f] = c0;
        s_lp[f] = make_float2(flae(CLOG + lca, l1mca - lognc),   // elsewhere
                              flae(lca,        l1mca - lognc));  // at x0 col
    }

    const int  j0  = tid * 4;
    const bool act = (j0 < DCOLS);

    // packed feature ids for this thread's 4 columns
    unsigned int fpack = 0;
    if (act) {
        #pragma unroll
        for (int q = 0; q < 4; q++) {
            int j = j0 + q;
            int g = j / 62, o = j - 62 * g;
            int k = (o < 2) ? 0 : (o < 6) ? 1 : (o < 14) ? 2 : (o < 30) ? 3 : 4;
            fpack |= (unsigned int)(5 * g + k) << (8 * q);
        }
    }
    __syncthreads();

    // -------- phase 1: z = gumbel + q_prior logits --------
    if (act) {
        float4 u4 = *reinterpret_cast<const float4*>(uni + (size_t)b * DCOLS + j0);
        const float* up = reinterpret_cast<const float*>(&u4);
        float4 z; float* zp = reinterpret_cast<float*>(&z);
        #pragma unroll
        for (int q = 0; q < 4; q++) {
            int j = j0 + q;
            int f = (fpack >> (8 * q)) & 0xff;
            float gum = -__logf(-__logf(up[q] + 1e-30f) + 1e-30f);
            float2 lp = s_lp[f];
            zp[q] = gum + ((j == s_col0[f]) ? lp.y : lp.x);
        }
        *reinterpret_cast<float4*>(sm + j0) = z;
    }
    __syncthreads();

    // per-segment argmax (first-max tie break; segment starts even -> float2)
    if (tid < FEAT) {
        int f = tid, g = f / 5, k = f - 5 * g;
        int start = g * 62 + c_off[k], n2 = (2 << k) >> 1;
        const float2* p2 = reinterpret_cast<const float2*>(sm + start);
        float best = -3.4e38f; int bi = 0;
        for (int i = 0; i < n2; i++) {
            float2 v = p2[i];
            if (v.x > best) { best = v.x; bi = 2 * i; }
            if (v.y > best) { best = v.y; bi = 2 * i + 1; }
        }
        w = start + bi;
        s_wbyte[f] = w * (DCOLS * 2);          // byte offset into fp16 W
    }
    __syncthreads();

    // -------- phase 2: gather-sum of 40 fp16 W rows (124 thr x 4 cols) -----
    if (act) {
        float ax = 0.f, ay = 0.f, az = 0.f, aw = 0.f;
        const char* Wb = (const char*)g_Whalf + (size_t)j0 * 2;
        #pragma unroll 8
        for (int f = 0; f < FEAT; f++) {
            uint2 v = *reinterpret_cast<const uint2*>(Wb + s_wbyte[f]);
            float2 f01 = __half22float2(*reinterpret_cast<__half2*>(&v.x));
            float2 f23 = __half22float2(*reinterpret_cast<__half2*>(&v.y));
            ax += f01.x; ay += f01.y; az += f23.x; aw += f23.y;
        }
        float4 cs = *reinterpret_cast<const float4*>(g_colsum + j0);
        float4 bb = *reinterpret_cast<const float4*>(bias + j0);
        float4 te = *reinterpret_cast<const float4*>(temb + (size_t)t * DCOLS + j0);
        float4 pr4;
        pr4.x = CLOG * (cs.x - ax) + bb.x + te.x;
        pr4.y = CLOG * (cs.y - ay) + bb.y + te.y;
        pr4.z = CLOG * (cs.z - az) + bb.z + te.z;
        pr4.w = CLOG * (cs.w - aw) + bb.w + te.w;
        *reinterpret_cast<float4*>(sm + j0) = pr4;
    }
    __syncthreads();

    // -------- scanner: lse(pred), true posterior, closed-form lse2, corrections --
    float kl = 0.f, dec = 0.f, pr = 0.f;
    if (tid < FEAT) {
        int f = tid, g = f / 5, k = f - 5 * g;
        int start = g * 62 + c_off[k], wdt = 2 << k, n2 = wdt >> 1;
        float lognc = c_lognc[k];

        const float2* p2 = reinterpret_cast<const float2*>(sm + start);
        float m = -3.4e38f;
        for (int i = 0; i < n2; i++) {
            float2 v = p2[i];
            m = fmaxf(m, fmaxf(v.x, v.y));
        }
        float s = 0.f;
        for (int i = 0; i < n2; i++) {
            float2 v = p2[i];
            s += __expf(v.x - m) + __expf(v.y - m);
        }
        float lse = m + __logf(s);

        // per-feature q_one_timestep values (only scanner needs them)
        const float la = g_la[t], l1ma = g_l1ma[t];
        float q1w = flae(la,        l1ma - lognc);
        float q1o = flae(CLOG + la, l1ma - lognc);

        // true posterior closed form
        float ev0 = (t == 0) ? 0.f  : flae(lca1,        l1mca1 - lognc);
        float evo = (t == 0) ? CLOG : flae(CLOG + lca1, l1mca1 - lognc);
        float un_oo = evo + q1o;
        float e0, e1, e2, klc, sum_p;
        if (c0 == w) {
            float un_b = ev0 + q1w;
            float mm = fmaxf(un_b, un_oo);
            float ss = __expf(un_b - mm) + (float)(wdt - 1) * __expf(un_oo - mm);
            float l2 = mm + __logf(ss);
            float lt1 = un_b - l2, lt0 = un_oo - l2;
            e0 = __expf(lt0); e1 = __expf(lt1); e2 = e1;
            klc = e1 * lt1 + (float)(wdt - 1) * e0 * lt0;
            sum_p = e1 + (float)(wdt - 1) * e0;
        } else {
            float un_c0 = ev0 + q1o;
            float un_w  = evo + q1w;
            float mm = fmaxf(fmaxf(un_c0, un_w), un_oo);
            float ss = __expf(un_c0 - mm) + __expf(un_w - mm) + (float)(wdt - 2) * __expf(un_oo - mm);
            float l2 = mm + __logf(ss);
            float lt0 = un_oo - l2, lt1 = un_c0 - l2, lt2 = un_w - l2;
            e0 = __expf(lt0); e1 = __expf(lt1); e2 = __expf(lt2);
            klc = e1 * lt1 + e2 * lt2 + (float)(wdt - 2) * e0 * lt0;
            sum_p = e1 + e2 + (float)(wdt - 2) * e0;
        }

        // est-posterior pieces at c0 and w + closed-form lse2
        float Bev = (t == 0) ? 0.f : __expf(l1mca1 - lognc);
        float pc0 = sm[c0], pw = sm[w];
        float smw  = __expf(pw  - lse);
        float smc0 = __expf(pc0 - lse);
        float ev_c0 = (t == 0) ? (pc0 - lse) : __logf(fmaf(smc0, Aev, Bev));
        float ev_w  = (t == 0) ? (pw  - lse) : __logf(fmaf(smw,  Aev, Bev));
        float qwE = __expf(q1w), qoE = __expf(q1o);
        float Z = Aev * fmaf(qwE - qoE, smw, qoE) + Bev * (qwE + (float)(wdt - 1) * qoE);
        float lse2 = __logf(Z);

        // scanner-side KL correction and decoder NLL
        float corr;
        float q1c0;
        if (c0 == w) {
            corr = klc + (lse2 - q1o) * sum_p - (e1 - e0) * ev_c0 - (q1w - q1o) * e1;
            q1c0 = q1w;
        } else {
            corr = klc + (lse2 - q1o) * sum_p - (e1 - e0) * ev_c0 - (e2 - e0) * ev_w
                 - (q1w - q1o) * e2;
            q1c0 = q1o;
        }
        kl  = corr;
        dec = lse2 - ev_c0 - q1c0;

        s_fc[f] = make_float4(lse, e0, Bev, 0.f);
    }
    if (tid < 5) {                              // kl_prior: 5 distinct values x 8 groups
        float lognc = c_lognc[tid];
        float wdt = (float)(2 << tid);
        float lcaT = g_lca[NT - 1], l1mcaT = g_l1mca[NT - 1];
        float lq0 = flae(lcaT,        l1mcaT - lognc);
        float lqo = flae(CLOG + lcaT, l1mcaT - lognc);
        pr = 8.0f * (__expf(lq0) * (lq0 + lognc) + (wdt - 1.0f) * __expf(lqo) * (lqo + lognc));
    }
    __syncthreads();

    // -------- dense accumulation: kl -= e0 * ev_j over all columns --------
    if (act) {
        float4 pv = *reinterpret_cast<const float4*>(sm + j0);
        const float* pp = reinterpret_cast<const float*>(&pv);
        #pragma unroll
        for (int q = 0; q < 4; q++) {
            int f = (fpack >> (8 * q)) & 0xff;
            float4 fc = s_fc[f];
            float lh = pp[q] - fc.x;
            float ev = (t == 0) ? lh : __logf(fmaf(__expf(lh), Aev, fc.z));
            kl -= fc.y * ev;
        }
    }

    float rk = wred(kl), rd = wred(dec), rp = wred(pr);
    int wid = tid >> 5, lane = tid & 31;
    if (lane == 0) { s_red[0][wid] = rk; s_red[1][wid] = rd; s_red[2][wid] = rp; }
    __syncthreads();
    if (tid == 0) {
        float K  = s_red[0][0] + s_red[0][1] + s_red[0][2] + s_red[0][3];
        float Dn = s_red[1][0] + s_red[1][1] + s_red[1][2] + s_red[1][3];
        float P  = s_red[2][0] + s_red[2][1] + s_red[2][2] + s_red[2][3];
        float diff = (t == 0) ? Dn : K;
        g_row_loss[b] = diff * 1000.0f + P;
    }
}

// ---------------------------------------------------------------------------
// Two-stage deterministic mean: 64 blocks x 128 threads (one float4 each,
// covering exactly 512 rows per block), then 1 block of 64.
// ---------------------------------------------------------------------------
__global__ void reduce1_kernel() {
    __shared__ double sd[4];
    int tid = threadIdx.x;                  // 128 threads
    const float4* rl = reinterpret_cast<const float4*>(g_row_loss + blockIdx.x * 512);
    float4 a = rl[tid];                     // float4 tid of this block's 128
    double s = (double)a.x + (double)a.y + (double)a.z + (double)a.w;
    #pragma unroll
    for (int o = 16; o; o >>= 1) s += __shfl_down_sync(0xffffffffu, s, o);
    if ((tid & 31) == 0) sd[tid >> 5] = s;
    __syncthreads();
    if (tid == 0) g_part[blockIdx.x] = sd[0] + sd[1] + sd[2] + sd[3];
}

__global__ void reduce2_kernel(float* __restrict__ out) {
    int tid = threadIdx.x;                  // 64 threads
    double s = g_part[tid];
    #pragma unroll
    for (int o = 16; o; o >>= 1) s += __shfl_down_sync(0xffffffffu, s, o);
    __shared__ double sd[2];
    if ((tid & 31) == 0) sd[tid >> 5] = s;
    __syncthreads();
    if (tid == 0) out[0] = (float)((sd[0] + sd[1]) / (double)BATCH);
}

extern "C" void kernel_launch(void* const* d_in, const int* in_sizes, int n_in,
                              void* d_out, int out_size)
{
    const int*   x0 = nullptr;  const int*   ts = nullptr;
    const float* un = nullptr;  const float* W  = nullptr;
    const float* bi = nullptr;  const float* te = nullptr;
    for (int i = 0; i < n_in; i++) {
        switch (in_sizes[i]) {
            case BATCH * FEAT:   x0 = (const int*)d_in[i];   break;
            case BATCH:          ts = (const int*)d_in[i];   break;
            case BATCH * DCOLS:  un = (const float*)d_in[i]; break;
            case DCOLS * DCOLS:  W  = (const float*)d_in[i]; break;
            case DCOLS:          bi = (const float*)d_in[i]; break;
            case NT * DCOLS:     te = (const float*)d_in[i]; break;
            default: break;
        }
    }
    float* out = (float*)d_out;

    dim3 gcs(4, 8);
    wcs_kernel<<<gcs, 128>>>(W);          // fp16 W + partial colsums
    sched_comb_kernel<<<5, 1024>>>();     // schedule + colsum combine
    ddpm_kernel<<<BATCH, 128>>>(x0, ts, un, bi, te);
    reduce1_kernel<<<64, 128>>>();        // 512 rows per block
    reduce2_kernel<<<1, 64>>>(out);
}